// round 15
// baseline (speedup 1.0000x reference)
#include <cuda_runtime.h>
#include <cuda_bf16.h>
#include <cstdint>

#define Tn   4096
#define En   256
#define Hh   256
#define G4   1024     // 4*Hh
#define Ln   20
#define NEGV -10000.0f

// ---------------- scratch (device globals; no allocations allowed) ----------
__device__ float g_xs[Tn * En];                    // 4 MB
__device__ float g_zx[2][Tn * G4];                 // 32 MB
__device__ float g_h[2][Tn * Hh];                  // 8 MB
__device__ float g_feats[Tn * Ln];                 // 320 KB
__device__ int   g_dummy_sink;

// ---------------- helpers ----------------------------------------------------
__device__ __forceinline__ uint32_t smem_u32(const void* p) {
    uint32_t a;
    asm("{ .reg .u64 t; cvta.to.shared.u64 t, %1; cvt.u32.u64 %0, t; }"
        : "=r"(a) : "l"(p));
    return a;
}

#define FFMA2(acc, w, h) \
    asm("fma.rn.f32x2 %0, %1, %2, %0;" : "+l"(acc) : "l"(w), "l"(h))

#define FADD2(d, a, b) \
    asm("add.rn.f32x2 %0, %1, %2;" : "=l"(d) : "l"(a), "l"(b))

__device__ __forceinline__ float unpack_sum(unsigned long long v) {
    float lo, hi;
    asm("mov.b64 {%0, %1}, %2;" : "=f"(lo), "=f"(hi) : "l"(v));
    return lo + hi;
}

__device__ __forceinline__ unsigned long long pack2(float lo, float hi) {
    unsigned long long v;
    asm("mov.b64 %0, {%1, %2};" : "=l"(v) : "f"(lo), "f"(hi));
    return v;
}

__device__ __forceinline__ void cluster_sync_() {
    asm volatile("barrier.cluster.arrive.aligned;" ::: "memory");
    asm volatile("barrier.cluster.wait.aligned;" ::: "memory");
}

__device__ __forceinline__ uint32_t ctarank_() {
    uint32_t r;
    asm("mov.u32 %0, %%cluster_ctarank;" : "=r"(r));
    return r;
}

// mbarrier wait on phase parity, cluster-scope acquire (remote async data).
__device__ __forceinline__ void wait_parity(uint32_t mbar, unsigned parity) {
    unsigned done = 0;
    asm volatile(
        "{ .reg .pred p;\n\t"
        "mbarrier.try_wait.parity.acquire.cluster.shared::cta.b64 p, [%1], %2;\n\t"
        "selp.b32 %0, 1, 0, p; }"
        : "=r"(done) : "r"(mbar), "r"(parity) : "memory");
    while (!done) {
        asm volatile(
            "{ .reg .pred p;\n\t"
            "mbarrier.try_wait.parity.acquire.cluster.shared::cta.b64 p, [%1], %2, 0x989680;\n\t"
            "selp.b32 %0, 1, 0, p; }"
            : "=r"(done) : "r"(mbar), "r"(parity) : "memory");
    }
}

// HW tanh (MUFU.TANH) + sigmoid built on it: 1 MUFU op per activation.
__device__ __forceinline__ float tanh_hw(float x) {
    float y;
    asm("tanh.approx.f32 %0, %1;" : "=f"(y) : "f"(x));
    return y;
}
__device__ __forceinline__ float sig_hw(float x) {
    return fmaf(0.5f, tanh_hw(0.5f * x), 0.5f);
}

__device__ __forceinline__ float fast_sigmoid(float x) {
    float e = __expf(-x);
    return __fdividef(1.0f, 1.0f + e);
}
__device__ __forceinline__ float fast_tanh(float x) {
    float e = __expf(-2.0f * x);
    return __fdividef(1.0f - e, 1.0f + e);
}

// ---------------- K0: embedding gather ---------------------------------------
__global__ void gather_kernel(const int* __restrict__ x,
                              const float* __restrict__ emb) {
    int t = blockIdx.x;
    int row = x[t];
    const float4* src = (const float4*)(emb + (size_t)row * En);
    float4* dst = (float4*)(g_xs + (size_t)t * En);
    dst[threadIdx.x] = src[threadIdx.x];
}

// ---------------- dummy: shifts ncu's positional capture slot by one --------
__global__ void profile_shift_kernel() {
    if (threadIdx.x == 1024) g_dummy_sink = 1;   // never true; pure no-op
}

// ---------------- K1: Zx = xs @ W_ih^T + b_ih + b_hh (both dirs) -------------
__global__ void zgemm_kernel(const float* __restrict__ wih_f,
                             const float* __restrict__ bih_f,
                             const float* __restrict__ bhh_f,
                             const float* __restrict__ wih_b,
                             const float* __restrict__ bih_b,
                             const float* __restrict__ bhh_b) {
    int dir = blockIdx.z;
    const float* W  = dir ? wih_b : wih_f;
    const float* b1 = dir ? bih_b : bih_f;
    const float* b2 = dir ? bhh_b : bhh_f;

    __shared__ float As[16][65];
    __shared__ float Bs[16][65];

    int tid = threadIdx.x;
    int t0 = blockIdx.x * 64;
    int r0 = blockIdx.y * 64;
    int tx = tid & 15;
    int ty = tid >> 4;
    int lt  = tid >> 2;          // loader row 0..63
    int lk4 = (tid & 3) * 4;     // loader k base 0,4,8,12

    float acc[4][4];
#pragma unroll
    for (int i = 0; i < 4; i++)
#pragma unroll
        for (int j = 0; j < 4; j++) acc[i][j] = 0.f;

    for (int k0 = 0; k0 < En; k0 += 16) {
        float4 av = *(const float4*)&g_xs[(size_t)(t0 + lt) * En + k0 + lk4];
        float4 bv = *(const float4*)&W[(size_t)(r0 + lt) * En + k0 + lk4];
        As[lk4 + 0][lt] = av.x; As[lk4 + 1][lt] = av.y;
        As[lk4 + 2][lt] = av.z; As[lk4 + 3][lt] = av.w;
        Bs[lk4 + 0][lt] = bv.x; Bs[lk4 + 1][lt] = bv.y;
        Bs[lk4 + 2][lt] = bv.z; Bs[lk4 + 3][lt] = bv.w;
        __syncthreads();
#pragma unroll
        for (int k = 0; k < 16; k++) {
            float a[4], b[4];
#pragma unroll
            for (int i = 0; i < 4; i++) a[i] = As[k][ty + 16 * i];
#pragma unroll
            for (int j = 0; j < 4; j++) b[j] = Bs[k][tx + 16 * j];
#pragma unroll
            for (int i = 0; i < 4; i++)
#pragma unroll
                for (int j = 0; j < 4; j++) acc[i][j] = fmaf(a[i], b[j], acc[i][j]);
        }
        __syncthreads();
    }
#pragma unroll
    for (int i = 0; i < 4; i++) {
        int tt = t0 + ty + 16 * i;
#pragma unroll
        for (int j = 0; j < 4; j++) {
            int rr = r0 + tx + 16 * j;
            g_zx[dir][(size_t)tt * G4 + rr] = acc[i][j] + b1[rr] + b2[rr];
        }
    }
}

// ============================================================================
// K2a: LSTM, TWO independent 16-CTA clusters (one per direction), grid=32.
// WARP-AUTONOMOUS design: warp w owns elements {2w, 2w+1} end-to-end.
//   lane: rowi = lane>>2 (8 gate-rows: gate=rowi>>1, elem=2w+(rowi&1)),
//         cg = lane&3 (64-col group, XOR-swizzled chunks => bank-conflict-free
//         4-address broadcast LDS).
//   After matvec: bfly-reduce over cg, shfl-gather gates to lanes 0/4,
//   activation + c state in-warp, lanes 0..15 send st.async.b64 to rank=lane.
// NO intra-CTA sync in the loop (no bar.sync, no smem z buffer).
// Protocol (2 tx mbarriers, 1024 B expect_tx, phase flip) unchanged.
// ============================================================================
__global__ void __launch_bounds__(256, 1)
lstm_dir16(const float* __restrict__ whh_f,
           const float* __restrict__ whh_b,
           const float* __restrict__ h0,
           const float* __restrict__ c0) {
    __shared__ __align__(16) float hbuf[2][Hh];      // double-buffered h state
    __shared__ __align__(8) unsigned long long bars[2];

    int tid  = threadIdx.x;
    int w    = tid >> 5;
    int lane = tid & 31;
    uint32_t r = ctarank_();
    int dir = blockIdx.x >> 4;       // cluster 0 = forward, cluster 1 = backward

    const float* W = dir ? whh_b : whh_f;
    const float* Z = g_zx[dir];
    float* H = g_h[dir];

    int rowi = lane >> 2;            // 0..7 row within warp
    int cg   = lane & 3;             // column group (64 cols)
    int gate = rowi >> 1;
    int elem = 2 * w + (rowi & 1);   // local element 0..15
    int grow = gate * 256 + (int)r * 16 + elem;   // global gate row

    // weights: chunk k holds cols cg*64 + (k^cg)*4 .. +4 (XOR swizzle)
    ulonglong2 wreg[16];
    {
        const float* wrow = W + (size_t)grow * Hh + cg * 64;
#pragma unroll
        for (int k = 0; k < 16; k++)
            wreg[k] = *(const ulonglong2*)(wrow + ((k ^ cg) << 2));
    }

    uint32_t bar0 = smem_u32(&bars[0]);
    if (tid == 0) {
        asm volatile("mbarrier.init.shared.b64 [%0], 1;" :: "r"(bar0) : "memory");
        asm volatile("mbarrier.init.shared.b64 [%0], 1;" :: "r"(bar0 + 8) : "memory");
    }
    hbuf[0][tid] = h0[dir * Hh + tid];
    bool actlane = ((lane & 3) == 0) && (rowi < 2);   // lanes 0 and 4
    float c = 0.f;
    if (actlane) c = c0[dir * Hh + r * 16 + elem];
    __syncthreads();
    cluster_sync_();   // bars + hbuf[0] visible cluster-wide

    // initial expect_tx: 1024 B per barrier (16 CTAs x 8 warps x 8 B)
    if (tid == 224) {
        asm volatile("mbarrier.arrive.expect_tx.shared.b64 _, [%0], 1024;"
                     :: "r"(bar0) : "memory");
        asm volatile("mbarrier.arrive.expect_tx.shared.b64 _, [%0], 1024;"
                     :: "r"(bar0 + 8) : "memory");
    }

    // send addresses: lanes 0..15 of every warp send this warp's 2 elems
    // (8 B at offset (r*16 + 2w)*4 in hbuf) to rank == lane.
    uint32_t rdK = 0, rbK = 0;
    if (lane < 16) {
        uint32_t ldst = smem_u32(&hbuf[0][r * 16 + 2 * w]);
        asm("mapa.shared::cluster.u32 %0, %1, %2;"
            : "=r"(rdK) : "r"(ldst), "r"(lane));
        asm("mapa.shared::cluster.u32 %0, %1, %2;"
            : "=r"(rbK) : "r"(bar0), "r"(lane));
    }

    // Zx pipeline (cg==0 lanes carry it; others keep 0)
    float zx_cur = 0.f;
    if (cg == 0) {
        int tt = dir ? (Tn - 1) : 0;
        zx_cur = __ldg(&Z[(size_t)tt * G4 + grow]);
    }

    unsigned ph0 = 0, ph1 = 0;
    for (int s = 0; s < Tn; s++) {
        int b  = s & 1;
        int nb = b ^ 1;
        int t  = dir ? (Tn - 1 - s) : s;

        // prefetch Zx for step s+1 (issued before the wait; latency hidden)
        float zx_nxt = 0.f;
        if (cg == 0 && s + 1 < Tn) {
            int tn_ = dir ? (Tn - 2 - s) : (s + 1);
            zx_nxt = __ldg(&Z[(size_t)tn_ * G4 + grow]);
        }

        if (s > 0) {
            if (b) { wait_parity(bar0 + 8, ph1); ph1 ^= 1; if (tid == 224)
                asm volatile("mbarrier.arrive.expect_tx.shared.b64 _, [%0], 1024;"
                             :: "r"(bar0 + 8) : "memory"); }
            else   { wait_parity(bar0, ph0);     ph0 ^= 1; if (tid == 224)
                asm volatile("mbarrier.arrive.expect_tx.shared.b64 _, [%0], 1024;"
                             :: "r"(bar0) : "memory"); }
        }

        // matvec over this lane's 64 columns (XOR-swizzled chunk order)
        float v;
        {
            const char* hb = (const char*)&hbuf[b][cg * 64];
            unsigned long long a[4] = {0, 0, 0, 0};
#pragma unroll
            for (int k = 0; k < 16; k++) {
                ulonglong2 hv = *(const ulonglong2*)(hb + ((k ^ cg) << 4));
                FFMA2(a[(2 * k) & 3], wreg[k].x, hv.x);
                FFMA2(a[(2 * k + 1) & 3], wreg[k].y, hv.y);
            }
            unsigned long long s0, s1, s2;
            FADD2(s0, a[0], a[2]); FADD2(s1, a[1], a[3]); FADD2(s2, s0, s1);
            v = unpack_sum(s2) + zx_cur;
        }
        zx_cur = zx_nxt;

        // reduce across the 4 column groups (lanes 4r..4r+3)
        v += __shfl_xor_sync(0xffffffffu, v, 1);
        v += __shfl_xor_sync(0xffffffffu, v, 2);

        // gather gates: lane L sees zi=v, zf=v@L+8, zg=v@L+16, zo=v@L+24
        float zf = __shfl_down_sync(0xffffffffu, v, 8);
        float zg = __shfl_down_sync(0xffffffffu, v, 16);
        float zo = __shfl_down_sync(0xffffffffu, v, 24);

        float hn = 0.f;
        if (actlane) {
            float ig = sig_hw(v);
            float fg = sig_hw(zf);
            float gg = tanh_hw(zg);
            float og = sig_hw(zo);
            c = fg * c + ig * gg;
            hn = og * tanh_hw(c);
        }

        if (s != Tn - 1) {
            float h0v = __shfl_sync(0xffffffffu, hn, 0);
            float h1v = __shfl_sync(0xffffffffu, hn, 4);
            if (lane < 16) {
                unsigned long long pk = pack2(h0v, h1v);
                asm volatile(
                    "st.async.shared::cluster.mbarrier::complete_tx::bytes.b64"
                    " [%0], %1, [%2];"
                    :: "r"(rdK + ((uint32_t)nb << 10)), "l"(pk),
                       "r"(rbK + ((uint32_t)nb << 3))
                    : "memory");
            }
        }
        if (actlane) H[(size_t)t * Hh + r * 16 + elem] = hn;
    }
    cluster_sync_();
}

// ============================================================================
// K2b: FALLBACK — proven R2 kernel (2 clusters of 8 CTAs, st.async.b32).
// ============================================================================
__global__ void __cluster_dims__(8, 1, 1) __launch_bounds__(256, 1)
lstm_fallback(const float* __restrict__ whh_f,
              const float* __restrict__ whh_b,
              const float* __restrict__ h0,
              const float* __restrict__ c0) {
    __shared__ __align__(16) float hbuf[2][Hh];
    __shared__ __align__(8) unsigned long long fullbar[2];
    __shared__ float z_s[128];

    int tid = threadIdx.x;
    int cta = blockIdx.x;
    int dir = cta >> 3;
    int r   = cta & 7;

    const float* W = dir ? whh_b : whh_f;
    const float* Z = g_zx[dir];
    float* H = g_h[dir];

    int lr   = tid >> 1;
    int half = tid & 1;
    int gate = lr >> 5;
    int j32  = lr & 31;
    int grow = gate * 256 + r * 32 + j32;

    ulonglong2 wreg[32];
    {
        const ulonglong2* wp =
            (const ulonglong2*)(W + (size_t)grow * Hh + half * 128);
#pragma unroll
        for (int i = 0; i < 32; i++) wreg[i] = wp[i];
    }

    uint32_t bar0 = smem_u32(&fullbar[0]);
    if (tid == 0) {
        asm volatile("mbarrier.init.shared.b64 [%0], 1;" :: "r"(bar0) : "memory");
        asm volatile("mbarrier.init.shared.b64 [%0], 1;" :: "r"(bar0 + 8) : "memory");
    }
    hbuf[0][tid] = h0[dir * Hh + tid];
    float c = 0.f;
    if (tid < 32) c = c0[dir * Hh + tid + r * 32];
    __syncthreads();
    cluster_sync_();

    if (tid == 32) {
        asm volatile("mbarrier.arrive.expect_tx.shared.b64 _, [%0], 1024;"
                     :: "r"(bar0) : "memory");
        asm volatile("mbarrier.arrive.expect_tx.shared.b64 _, [%0], 1024;"
                     :: "r"(bar0 + 8) : "memory");
    }

    uint32_t rbuf0[8], rbar0[8];
    if (tid < 32) {
        uint32_t lbuf = smem_u32(&hbuf[0][r * 32 + tid]);
#pragma unroll
        for (int rr = 0; rr < 8; rr++) {
            asm("mapa.shared::cluster.u32 %0, %1, %2;"
                : "=r"(rbuf0[rr]) : "r"(lbuf), "r"(rr));
            asm("mapa.shared::cluster.u32 %0, %1, %2;"
                : "=r"(rbar0[rr]) : "r"(bar0), "r"(rr));
        }
    }

    unsigned ph0 = 0, ph1 = 0;
    for (int s = 0; s < Tn; s++) {
        int t = dir ? (Tn - 1 - s) : s;
        int b = s & 1;

        if (s > 0) {
            if (b) { wait_parity(bar0 + 8, ph1); ph1 ^= 1; if (tid == 32)
                asm volatile("mbarrier.arrive.expect_tx.shared.b64 _, [%0], 1024;"
                             :: "r"(bar0 + 8) : "memory"); }
            else   { wait_parity(bar0, ph0);     ph0 ^= 1; if (tid == 32)
                asm volatile("mbarrier.arrive.expect_tx.shared.b64 _, [%0], 1024;"
                             :: "r"(bar0) : "memory"); }
        }

        float zxv = 0.f;
        if (half == 0) zxv = __ldg(&Z[(size_t)t * G4 + grow]);

        const ulonglong2* hp = (const ulonglong2*)&hbuf[b][half * 128];
        unsigned long long a[8] = {0, 0, 0, 0, 0, 0, 0, 0};
#pragma unroll
        for (int i = 0; i < 32; i++) {
            ulonglong2 hv = hp[i];
            FFMA2(a[(2 * i) & 7], wreg[i].x, hv.x);
            FFMA2(a[(2 * i + 1) & 7], wreg[i].y, hv.y);
        }
        unsigned long long b0_, b1_, b2_, b3_, t0_, t1_, t2_;
        FADD2(b0_, a[0], a[4]); FADD2(b1_, a[1], a[5]);
        FADD2(b2_, a[2], a[6]); FADD2(b3_, a[3], a[7]);
        FADD2(t0_, b0_, b2_); FADD2(t1_, b1_, b3_); FADD2(t2_, t0_, t1_);
        float v = unpack_sum(t2_);
        v += __shfl_xor_sync(0xffffffffu, v, 1);
        if (half == 0) z_s[lr] = v + zxv;
        __syncthreads();

        if (tid < 32) {
            float zi = z_s[tid];
            float zf = z_s[32 + tid];
            float zg = z_s[64 + tid];
            float zo = z_s[96 + tid];
            float ig = fast_sigmoid(zi);
            float fg = fast_sigmoid(zf);
            float og = fast_sigmoid(zo);
            float gg = fast_tanh(zg);
            c = fg * c + ig * gg;
            float hn = og * fast_tanh(c);
            H[(size_t)t * Hh + r * 32 + tid] = hn;

            if (s != Tn - 1) {
                int nb = (s + 1) & 1;
                uint32_t hbits = __float_as_uint(hn);
                uint32_t boff = (uint32_t)nb << 10;
                uint32_t moff = (uint32_t)nb << 3;
#pragma unroll
                for (int rr = 0; rr < 8; rr++) {
                    asm volatile(
                        "st.async.shared::cluster.mbarrier::complete_tx::bytes.b32"
                        " [%0], %1, [%2];"
                        :: "r"(rbuf0[rr] + boff), "r"(hbits), "r"(rbar0[rr] + moff)
                        : "memory");
                }
            }
        }
    }
    cluster_sync_();
}

// ---------------- K3: feats = [h_f, h_b] @ w_out^T + b_out -------------------
__global__ void feats_kernel(const float* __restrict__ wout,
                             const float* __restrict__ bout) {
    int t = blockIdx.x;
    int w = threadIdx.x >> 5;
    int lane = threadIdx.x & 31;
    const float* h1 = g_h[0] + (size_t)t * Hh;
    const float* h2 = g_h[1] + (size_t)t * Hh;
    const float* wr = wout + (size_t)w * 512;
    float sum = 0.f;
#pragma unroll
    for (int k = lane; k < 256; k += 32) sum = fmaf(h1[k], wr[k], sum);
#pragma unroll
    for (int k = lane; k < 256; k += 32) sum = fmaf(h2[k], wr[256 + k], sum);
#pragma unroll
    for (int o = 16; o; o >>= 1) sum += __shfl_xor_sync(0xffffffffu, sum, o);
    if (lane == 0) g_feats[(size_t)t * Ln + w] = sum + bout[w];
}

// ---------------- K4: Viterbi + backtrack (single warp) ----------------------
__global__ void viterbi_kernel(const float* __restrict__ trans,
                               float* __restrict__ out, int out_size) {
    extern __shared__ unsigned char bp[];   // [Tn][Ln]
    int lane = threadIdx.x;
    int to = lane;
    bool act = (to < Ln);

    float tr[Ln];
#pragma unroll
    for (int f = 0; f < Ln; f++) tr[f] = act ? trans[to * Ln + f] : -1e30f;
    float trstop = act ? trans[19 * Ln + to] : -1e30f;

    float alpha = (to == 18) ? 0.f : NEGV;

    float fr0 = act ? g_feats[0 * Ln + to] : 0.f;
    float fr1 = act ? g_feats[1 * Ln + to] : 0.f;

    for (int t = 0; t < Tn; t++) {
        float frn = (act && t + 2 < Tn) ? g_feats[(size_t)(t + 2) * Ln + to] : 0.f;

        float s[Ln];
#pragma unroll
        for (int f = 0; f < Ln; f++)
            s[f] = __shfl_sync(0xffffffffu, alpha, f) + tr[f];

        float m[10];
#pragma unroll
        for (int i = 0; i < 10; i++) m[i] = fmaxf(s[i], s[i + 10]);
#pragma unroll
        for (int i = 0; i < 5; i++) m[i] = fmaxf(m[i], m[i + 5]);
        float best = fmaxf(fmaxf(fmaxf(m[0], m[1]), fmaxf(m[2], m[3])), m[4]);

        unsigned msk = 0;
#pragma unroll
        for (int f = 0; f < Ln; f++)
            msk |= (s[f] == best) ? (1u << f) : 0u;
        int arg = __ffs(msk) - 1;

        if (act) bp[(size_t)t * Ln + to] = (unsigned char)arg;
        alpha = best + fr0;
        fr0 = fr1;
        fr1 = frn;
    }

    float fin = act ? (alpha + trstop) : -1e30f;
    float best = fin;
#pragma unroll
    for (int o = 16; o; o >>= 1) best = fmaxf(best, __shfl_xor_sync(0xffffffffu, best, o));
    unsigned msk = __ballot_sync(0xffffffffu, fin == best);
    int best_last = __ffs(msk) - 1;

    if (lane == 0) {
        float* po = out;
        if (out_size >= Tn + 1) { out[0] = best; po = out + 1; }
        int cur = best_last;
        po[Tn - 1] = (float)cur;
        for (int t = Tn - 1; t >= 1; t--) {
            cur = bp[(size_t)t * Ln + cur];
            po[t - 1] = (float)cur;
        }
        if (out_size == 1) out[0] = best;
    }
}

// ---------------- launch ------------------------------------------------------
extern "C" void kernel_launch(void* const* d_in, const int* in_sizes, int n_in,
                              void* d_out, int out_size) {
    const int*   x      = (const int*)  d_in[0];
    const float* emb    = (const float*)d_in[1];
    const float* wih_f  = (const float*)d_in[2];
    const float* whh_f  = (const float*)d_in[3];
    const float* bih_f  = (const float*)d_in[4];
    const float* bhh_f  = (const float*)d_in[5];
    const float* wih_b  = (const float*)d_in[6];
    const float* whh_b  = (const float*)d_in[7];
    const float* bih_b  = (const float*)d_in[8];
    const float* bhh_b  = (const float*)d_in[9];
    const float* wout   = (const float*)d_in[10];
    const float* bout   = (const float*)d_in[11];
    const float* trans  = (const float*)d_in[12];
    const float* h0     = (const float*)d_in[13];
    const float* c0     = (const float*)d_in[14];
    float* out = (float*)d_out;

    gather_kernel<<<Tn, 64>>>(x, emb);

    // keeps ncu's positional capture slot on lstm_dir16
    profile_shift_kernel<<<1, 32>>>();

    dim3 zg(Tn / 64, G4 / 64, 2);
    zgemm_kernel<<<zg, 256>>>(wih_f, bih_f, bhh_f, wih_b, bih_b, bhh_b);

    // two 16-CTA clusters (one per direction); fallback to proven 8-CTA kernel
    cudaFuncSetAttribute(lstm_dir16,
                         cudaFuncAttributeNonPortableClusterSizeAllowed, 1);
    cudaLaunchConfig_t cfg = {};
    cfg.gridDim = dim3(32, 1, 1);
    cfg.blockDim = dim3(256, 1, 1);
    cfg.dynamicSmemBytes = 0;
    cudaLaunchAttribute attrs[1];
    attrs[0].id = cudaLaunchAttributeClusterDimension;
    attrs[0].val.clusterDim = {16, 1, 1};
    cfg.attrs = attrs;
    cfg.numAttrs = 1;
    cudaError_t e = cudaLaunchKernelEx(&cfg, lstm_dir16, whh_f, whh_b, h0, c0);
    if (e != cudaSuccess) {
        (void)cudaGetLastError();   // clear
        lstm_fallback<<<16, 256>>>(whh_f, whh_b, h0, c0);
    }

    feats_kernel<<<Tn, Ln * 32>>>(wout, bout);

    int vit_smem = Tn * Ln;
    cudaFuncSetAttribute(viterbi_kernel,
                         cudaFuncAttributeMaxDynamicSharedMemorySize, vit_smem);
    viterbi_kernel<<<1, 32, vit_smem>>>(trans, out, out_size);
}

// round 16
// speedup vs baseline: 1.4824x; 1.4824x over previous
#include <cuda_runtime.h>
#include <cuda_bf16.h>
#include <cstdint>

#define Tn   4096
#define En   256
#define Hh   256
#define G4   1024     // 4*Hh
#define Ln   20
#define NEGV -10000.0f

// ---------------- scratch (device globals; no allocations allowed) ----------
__device__ float g_xs[Tn * En];                    // 4 MB
__device__ float g_zx[2][Tn * G4];                 // 32 MB
__device__ float g_h[2][Tn * Hh];                  // 8 MB
__device__ float g_feats[Tn * Ln];                 // 320 KB
__device__ int   g_dummy_sink;

// ---------------- helpers ----------------------------------------------------
__device__ __forceinline__ uint32_t smem_u32(const void* p) {
    uint32_t a;
    asm("{ .reg .u64 t; cvta.to.shared.u64 t, %1; cvt.u32.u64 %0, t; }"
        : "=r"(a) : "l"(p));
    return a;
}

#define FFMA2(acc, w, h) \
    asm("fma.rn.f32x2 %0, %1, %2, %0;" : "+l"(acc) : "l"(w), "l"(h))

#define FADD2(d, a, b) \
    asm("add.rn.f32x2 %0, %1, %2;" : "=l"(d) : "l"(a), "l"(b))

__device__ __forceinline__ float unpack_sum(unsigned long long v) {
    float lo, hi;
    asm("mov.b64 {%0, %1}, %2;" : "=f"(lo), "=f"(hi) : "l"(v));
    return lo + hi;
}

__device__ __forceinline__ void cluster_sync_() {
    asm volatile("barrier.cluster.arrive.aligned;" ::: "memory");
    asm volatile("barrier.cluster.wait.aligned;" ::: "memory");
}

__device__ __forceinline__ uint32_t ctarank_() {
    uint32_t r;
    asm("mov.u32 %0, %%cluster_ctarank;" : "=r"(r));
    return r;
}

// mbarrier wait on phase parity, cluster-scope acquire (remote async data).
__device__ __forceinline__ void wait_parity(uint32_t mbar, unsigned parity) {
    unsigned done = 0;
    asm volatile(
        "{ .reg .pred p;\n\t"
        "mbarrier.try_wait.parity.acquire.cluster.shared::cta.b64 p, [%1], %2;\n\t"
        "selp.b32 %0, 1, 0, p; }"
        : "=r"(done) : "r"(mbar), "r"(parity) : "memory");
    while (!done) {
        asm volatile(
            "{ .reg .pred p;\n\t"
            "mbarrier.try_wait.parity.acquire.cluster.shared::cta.b64 p, [%1], %2, 0x989680;\n\t"
            "selp.b32 %0, 1, 0, p; }"
            : "=r"(done) : "r"(mbar), "r"(parity) : "memory");
    }
}

// HW tanh (MUFU.TANH) + sigmoid built on it: 1 MUFU op per activation.
__device__ __forceinline__ float tanh_hw(float x) {
    float y;
    asm("tanh.approx.f32 %0, %1;" : "=f"(y) : "f"(x));
    return y;
}
__device__ __forceinline__ float sig_hw(float x) {
    return fmaf(0.5f, tanh_hw(0.5f * x), 0.5f);
}

__device__ __forceinline__ float fast_sigmoid(float x) {
    float e = __expf(-x);
    return __fdividef(1.0f, 1.0f + e);
}
__device__ __forceinline__ float fast_tanh(float x) {
    float e = __expf(-2.0f * x);
    return __fdividef(1.0f - e, 1.0f + e);
}

// ---------------- K0: embedding gather ---------------------------------------
__global__ void gather_kernel(const int* __restrict__ x,
                              const float* __restrict__ emb) {
    int t = blockIdx.x;
    int row = x[t];
    const float4* src = (const float4*)(emb + (size_t)row * En);
    float4* dst = (float4*)(g_xs + (size_t)t * En);
    dst[threadIdx.x] = src[threadIdx.x];
}

// ---------------- dummy: shifts ncu's positional capture slot by one --------
__global__ void profile_shift_kernel() {
    if (threadIdx.x == 1024) g_dummy_sink = 1;   // never true; pure no-op
}

// ---------------- K1: Zx = xs @ W_ih^T + b_ih + b_hh (both dirs) -------------
__global__ void zgemm_kernel(const float* __restrict__ wih_f,
                             const float* __restrict__ bih_f,
                             const float* __restrict__ bhh_f,
                             const float* __restrict__ wih_b,
                             const float* __restrict__ bih_b,
                             const float* __restrict__ bhh_b) {
    int dir = blockIdx.z;
    const float* W  = dir ? wih_b : wih_f;
    const float* b1 = dir ? bih_b : bih_f;
    const float* b2 = dir ? bhh_b : bhh_f;

    __shared__ float As[16][65];
    __shared__ float Bs[16][65];

    int tid = threadIdx.x;
    int t0 = blockIdx.x * 64;
    int r0 = blockIdx.y * 64;
    int tx = tid & 15;
    int ty = tid >> 4;
    int lt  = tid >> 2;          // loader row 0..63
    int lk4 = (tid & 3) * 4;     // loader k base 0,4,8,12

    float acc[4][4];
#pragma unroll
    for (int i = 0; i < 4; i++)
#pragma unroll
        for (int j = 0; j < 4; j++) acc[i][j] = 0.f;

    for (int k0 = 0; k0 < En; k0 += 16) {
        float4 av = *(const float4*)&g_xs[(size_t)(t0 + lt) * En + k0 + lk4];
        float4 bv = *(const float4*)&W[(size_t)(r0 + lt) * En + k0 + lk4];
        As[lk4 + 0][lt] = av.x; As[lk4 + 1][lt] = av.y;
        As[lk4 + 2][lt] = av.z; As[lk4 + 3][lt] = av.w;
        Bs[lk4 + 0][lt] = bv.x; Bs[lk4 + 1][lt] = bv.y;
        Bs[lk4 + 2][lt] = bv.z; Bs[lk4 + 3][lt] = bv.w;
        __syncthreads();
#pragma unroll
        for (int k = 0; k < 16; k++) {
            float a[4], b[4];
#pragma unroll
            for (int i = 0; i < 4; i++) a[i] = As[k][ty + 16 * i];
#pragma unroll
            for (int j = 0; j < 4; j++) b[j] = Bs[k][tx + 16 * j];
#pragma unroll
            for (int i = 0; i < 4; i++)
#pragma unroll
                for (int j = 0; j < 4; j++) acc[i][j] = fmaf(a[i], b[j], acc[i][j]);
        }
        __syncthreads();
    }
#pragma unroll
    for (int i = 0; i < 4; i++) {
        int tt = t0 + ty + 16 * i;
#pragma unroll
        for (int j = 0; j < 4; j++) {
            int rr = r0 + tx + 16 * j;
            g_zx[dir][(size_t)tt * G4 + rr] = acc[i][j] + b1[rr] + b2[rr];
        }
    }
}

// ============================================================================
// K2a: LSTM, TWO independent 16-CTA clusters (one per direction), grid=32.
// EXACT R12 kernel (best measured: 3333 us total). Do not touch.
// ============================================================================
__global__ void __launch_bounds__(256, 1)
lstm_dir16(const float* __restrict__ whh_f,
           const float* __restrict__ whh_b,
           const float* __restrict__ h0,
           const float* __restrict__ c0) {
    __shared__ __align__(16) float hbuf[2][Hh];      // double-buffered h state
    __shared__ __align__(16) float z4t[64][4];       // [row][quarter] partials
    __shared__ __align__(8) unsigned long long bars[2];

    int tid  = threadIdx.x;
    int w    = tid >> 5;
    int lane = tid & 31;
    uint32_t r = ctarank_();
    int dir = blockIdx.x >> 4;       // cluster 0 = forward, cluster 1 = backward

    const float* W = dir ? whh_b : whh_f;
    const float* Z = g_zx[dir];
    float* H = g_h[dir];

    int q    = w & 3;                // column quarter (warp-uniform)
    int rh   = w >> 2;               // row half
    int row  = rh * 32 + lane;       // 0..63
    int gate = row >> 4;
    int e    = row & 15;
    int grow = gate * 256 + (int)r * 16 + e;   // global gate row

    // 64 weights/thread in registers (16 x f32x2-pair)
    ulonglong2 wreg[16];
    {
        const ulonglong2* wp =
            (const ulonglong2*)(W + (size_t)grow * Hh + q * 64);
#pragma unroll
        for (int i = 0; i < 16; i++) wreg[i] = wp[i];
    }

    uint32_t bar0 = smem_u32(&bars[0]);
    if (tid == 0) {
        asm volatile("mbarrier.init.shared.b64 [%0], 1;" :: "r"(bar0) : "memory");
        asm volatile("mbarrier.init.shared.b64 [%0], 1;" :: "r"(bar0 + 8) : "memory");
    }
    hbuf[0][tid] = h0[dir * Hh + tid];
    float c = 0.f;
    if (w == 0 && lane < 16) c = c0[dir * Hh + r * 16 + lane];
    __syncthreads();
    cluster_sync_();   // bars + hbuf[0] visible cluster-wide

    // initial expect_tx: 1024 B per barrier (64 msgs x 16 B)
    if (tid == 224) {
        asm volatile("mbarrier.arrive.expect_tx.shared.b64 _, [%0], 1024;"
                     :: "r"(bar0) : "memory");
        asm volatile("mbarrier.arrive.expect_tx.shared.b64 _, [%0], 1024;"
                     :: "r"(bar0 + 8) : "memory");
    }

    // exchange lane map: lane L (0..15): group g=L&3 (h elems g*4..g*4+3),
    // targets ranks (L>>2)+4j, j=0..3. Each rank receives all 4 groups from
    // 4 distinct lanes => 64 msgs x 16 B = 1024 B per barrier.
    uint32_t rd4[4], rb4[4];
    int g4 = lane & 3;
    if (w == 0 && lane < 16) {
        uint32_t ldst = smem_u32(&hbuf[0][r * 16 + g4 * 4]);
#pragma unroll
        for (int j = 0; j < 4; j++) {
            int k = (lane >> 2) + j * 4;
            asm("mapa.shared::cluster.u32 %0, %1, %2;"
                : "=r"(rd4[j]) : "r"(ldst), "r"(k));
            asm("mapa.shared::cluster.u32 %0, %1, %2;"
                : "=r"(rb4[j]) : "r"(bar0), "r"(k));
        }
    }

    // Zx software pipeline: current value in register, next prefetched pre-wait
    float zx_cur = 0.f;
    if (q == 0) {
        int tt = dir ? (Tn - 1) : 0;
        zx_cur = __ldg(&Z[(size_t)tt * G4 + grow]);
    }

    unsigned ph0 = 0, ph1 = 0;
    for (int s = 0; s < Tn; s++) {
        int b  = s & 1;
        int nb = b ^ 1;
        int t  = dir ? (Tn - 1 - s) : s;

        // prefetch Zx for step s+1 (issued before the wait; latency hidden)
        float zx_nxt = 0.f;
        if (q == 0 && s + 1 < Tn) {
            int tn_ = dir ? (Tn - 2 - s) : (s + 1);
            zx_nxt = __ldg(&Z[(size_t)tn_ * G4 + grow]);
        }

        if (s > 0) {
            if (b) { wait_parity(bar0 + 8, ph1); ph1 ^= 1; if (tid == 224)
                asm volatile("mbarrier.arrive.expect_tx.shared.b64 _, [%0], 1024;"
                             :: "r"(bar0 + 8) : "memory"); }
            else   { wait_parity(bar0, ph0);     ph0 ^= 1; if (tid == 224)
                asm volatile("mbarrier.arrive.expect_tx.shared.b64 _, [%0], 1024;"
                             :: "r"(bar0) : "memory"); }
        }

        // broadcast LDS matvec over this thread's 64 columns
        {
            const ulonglong2* hp = (const ulonglong2*)&hbuf[b][q * 64];
            unsigned long long a[4] = {0, 0, 0, 0};
#pragma unroll
            for (int i = 0; i < 16; i++) {
                ulonglong2 hv = hp[i];
                FFMA2(a[(2 * i) & 3], wreg[i].x, hv.x);
                FFMA2(a[(2 * i + 1) & 3], wreg[i].y, hv.y);
            }
            unsigned long long s0, s1, s2;
            FADD2(s0, a[0], a[2]); FADD2(s1, a[1], a[3]); FADD2(s2, s0, s1);
            z4t[row][q] = unpack_sum(s2) + zx_cur;
        }
        zx_cur = zx_nxt;

        // asymmetric barrier: producers signal and run ahead to the next
        // mbarrier wait; only warp 0 (the consumer) blocks here.
        if (w == 0) {
            asm volatile("bar.sync 1, 256;" ::: "memory");
        } else {
            asm volatile("bar.arrive 1, 256;" ::: "memory");
        }

        if (w == 0 && lane < 16) {
            float4 vi = *(const float4*)z4t[lane];
            float4 vf = *(const float4*)z4t[16 + lane];
            float4 vg = *(const float4*)z4t[32 + lane];
            float4 vo = *(const float4*)z4t[48 + lane];
            float zi = (vi.x + vi.y) + (vi.z + vi.w);
            float zf = (vf.x + vf.y) + (vf.z + vf.w);
            float zg = (vg.x + vg.y) + (vg.z + vg.w);
            float zo = (vo.x + vo.y) + (vo.z + vo.w);
            float ig = sig_hw(zi);
            float fg = sig_hw(zf);
            float gg = tanh_hw(zg);
            float og = sig_hw(zo);
            c = fg * c + ig * gg;
            float hn = og * tanh_hw(c);

            if (s != Tn - 1) {
                float a0 = __shfl_sync(0x0000ffffu, hn, g4 * 4);
                float a1 = __shfl_sync(0x0000ffffu, hn, g4 * 4 + 1);
                float a2 = __shfl_sync(0x0000ffffu, hn, g4 * 4 + 2);
                float a3 = __shfl_sync(0x0000ffffu, hn, g4 * 4 + 3);
                uint32_t doff = (uint32_t)nb << 10;   // hbuf stride 1024 B
                uint32_t boff = (uint32_t)nb << 3;    // bar stride 8 B
#pragma unroll
                for (int j = 0; j < 4; j++)
                    asm volatile(
                        "st.async.shared::cluster.mbarrier::complete_tx::bytes"
                        ".v4.b32 [%0], {%1, %2, %3, %4}, [%5];"
                        :: "r"(rd4[j] + doff),
                           "r"(__float_as_uint(a0)), "r"(__float_as_uint(a1)),
                           "r"(__float_as_uint(a2)), "r"(__float_as_uint(a3)),
                           "r"(rb4[j] + boff)
                        : "memory");
            }
            H[(size_t)t * Hh + r * 16 + lane] = hn;
        }
    }
    cluster_sync_();
}

// ============================================================================
// K2b: FALLBACK — proven R2 kernel (2 clusters of 8 CTAs, st.async.b32).
// ============================================================================
__global__ void __cluster_dims__(8, 1, 1) __launch_bounds__(256, 1)
lstm_fallback(const float* __restrict__ whh_f,
              const float* __restrict__ whh_b,
              const float* __restrict__ h0,
              const float* __restrict__ c0) {
    __shared__ __align__(16) float hbuf[2][Hh];
    __shared__ __align__(8) unsigned long long fullbar[2];
    __shared__ float z_s[128];

    int tid = threadIdx.x;
    int cta = blockIdx.x;
    int dir = cta >> 3;
    int r   = cta & 7;

    const float* W = dir ? whh_b : whh_f;
    const float* Z = g_zx[dir];
    float* H = g_h[dir];

    int lr   = tid >> 1;
    int half = tid & 1;
    int gate = lr >> 5;
    int j32  = lr & 31;
    int grow = gate * 256 + r * 32 + j32;

    ulonglong2 wreg[32];
    {
        const ulonglong2* wp =
            (const ulonglong2*)(W + (size_t)grow * Hh + half * 128);
#pragma unroll
        for (int i = 0; i < 32; i++) wreg[i] = wp[i];
    }

    uint32_t bar0 = smem_u32(&fullbar[0]);
    if (tid == 0) {
        asm volatile("mbarrier.init.shared.b64 [%0], 1;" :: "r"(bar0) : "memory");
        asm volatile("mbarrier.init.shared.b64 [%0], 1;" :: "r"(bar0 + 8) : "memory");
    }
    hbuf[0][tid] = h0[dir * Hh + tid];
    float c = 0.f;
    if (tid < 32) c = c0[dir * Hh + tid + r * 32];
    __syncthreads();
    cluster_sync_();

    if (tid == 32) {
        asm volatile("mbarrier.arrive.expect_tx.shared.b64 _, [%0], 1024;"
                     :: "r"(bar0) : "memory");
        asm volatile("mbarrier.arrive.expect_tx.shared.b64 _, [%0], 1024;"
                     :: "r"(bar0 + 8) : "memory");
    }

    uint32_t rbuf0[8], rbar0[8];
    if (tid < 32) {
        uint32_t lbuf = smem_u32(&hbuf[0][r * 32 + tid]);
#pragma unroll
        for (int rr = 0; rr < 8; rr++) {
            asm("mapa.shared::cluster.u32 %0, %1, %2;"
                : "=r"(rbuf0[rr]) : "r"(lbuf), "r"(rr));
            asm("mapa.shared::cluster.u32 %0, %1, %2;"
                : "=r"(rbar0[rr]) : "r"(bar0), "r"(rr));
        }
    }

    unsigned ph0 = 0, ph1 = 0;
    for (int s = 0; s < Tn; s++) {
        int t = dir ? (Tn - 1 - s) : s;
        int b = s & 1;

        if (s > 0) {
            if (b) { wait_parity(bar0 + 8, ph1); ph1 ^= 1; if (tid == 32)
                asm volatile("mbarrier.arrive.expect_tx.shared.b64 _, [%0], 1024;"
                             :: "r"(bar0 + 8) : "memory"); }
            else   { wait_parity(bar0, ph0);     ph0 ^= 1; if (tid == 32)
                asm volatile("mbarrier.arrive.expect_tx.shared.b64 _, [%0], 1024;"
                             :: "r"(bar0) : "memory"); }
        }

        float zxv = 0.f;
        if (half == 0) zxv = __ldg(&Z[(size_t)t * G4 + grow]);

        const ulonglong2* hp = (const ulonglong2*)&hbuf[b][half * 128];
        unsigned long long a[8] = {0, 0, 0, 0, 0, 0, 0, 0};
#pragma unroll
        for (int i = 0; i < 32; i++) {
            ulonglong2 hv = hp[i];
            FFMA2(a[(2 * i) & 7], wreg[i].x, hv.x);
            FFMA2(a[(2 * i + 1) & 7], wreg[i].y, hv.y);
        }
        unsigned long long b0_, b1_, b2_, b3_, t0_, t1_, t2_;
        FADD2(b0_, a[0], a[4]); FADD2(b1_, a[1], a[5]);
        FADD2(b2_, a[2], a[6]); FADD2(b3_, a[3], a[7]);
        FADD2(t0_, b0_, b2_); FADD2(t1_, b1_, b3_); FADD2(t2_, t0_, t1_);
        float v = unpack_sum(t2_);
        v += __shfl_xor_sync(0xffffffffu, v, 1);
        if (half == 0) z_s[lr] = v + zxv;
        __syncthreads();

        if (tid < 32) {
            float zi = z_s[tid];
            float zf = z_s[32 + tid];
            float zg = z_s[64 + tid];
            float zo = z_s[96 + tid];
            float ig = fast_sigmoid(zi);
            float fg = fast_sigmoid(zf);
            float og = fast_sigmoid(zo);
            float gg = fast_tanh(zg);
            c = fg * c + ig * gg;
            float hn = og * fast_tanh(c);
            H[(size_t)t * Hh + r * 32 + tid] = hn;

            if (s != Tn - 1) {
                int nb = (s + 1) & 1;
                uint32_t hbits = __float_as_uint(hn);
                uint32_t boff = (uint32_t)nb << 10;
                uint32_t moff = (uint32_t)nb << 3;
#pragma unroll
                for (int rr = 0; rr < 8; rr++) {
                    asm volatile(
                        "st.async.shared::cluster.mbarrier::complete_tx::bytes.b32"
                        " [%0], %1, [%2];"
                        :: "r"(rbuf0[rr] + boff), "r"(hbits), "r"(rbar0[rr] + moff)
                        : "memory");
                }
            }
        }
    }
    cluster_sync_();
}

// ---------------- K3: feats = [h_f, h_b] @ w_out^T + b_out -------------------
__global__ void feats_kernel(const float* __restrict__ wout,
                             const float* __restrict__ bout) {
    int t = blockIdx.x;
    int w = threadIdx.x >> 5;
    int lane = threadIdx.x & 31;
    const float* h1 = g_h[0] + (size_t)t * Hh;
    const float* h2 = g_h[1] + (size_t)t * Hh;
    const float* wr = wout + (size_t)w * 512;
    float sum = 0.f;
#pragma unroll
    for (int k = lane; k < 256; k += 32) sum = fmaf(h1[k], wr[k], sum);
#pragma unroll
    for (int k = lane; k < 256; k += 32) sum = fmaf(h2[k], wr[256 + k], sum);
#pragma unroll
    for (int o = 16; o; o >>= 1) sum += __shfl_xor_sync(0xffffffffu, sum, o);
    if (lane == 0) g_feats[(size_t)t * Ln + w] = sum + bout[w];
}

// ---------------- K4: Viterbi + backtrack (single warp) ----------------------
// alpha broadcast via double-buffered smem (5 x LDS.128 per step) instead of
// 20 sequential SHFLs. Values bit-identical => tie semantics preserved.
__global__ void viterbi_kernel(const float* __restrict__ trans,
                               float* __restrict__ out, int out_size) {
    extern __shared__ unsigned char dynsm[];
    unsigned char* bp = dynsm;                       // [Tn][Ln] backpointers
    __shared__ __align__(16) float al[2][20];

    int lane = threadIdx.x;
    int to = lane;
    bool act = (to < Ln);

    float tr[Ln];
#pragma unroll
    for (int f = 0; f < Ln; f++) tr[f] = act ? trans[to * Ln + f] : -1e30f;
    float trstop = act ? trans[19 * Ln + to] : -1e30f;

    float alpha = (to == 18) ? 0.f : NEGV;
    if (act) al[0][to] = alpha;
    __syncwarp();

    float fr0 = act ? g_feats[0 * Ln + to] : 0.f;
    float fr1 = act ? g_feats[1 * Ln + to] : 0.f;

    for (int t = 0; t < Tn; t++) {
        int b  = t & 1;
        int nb = b ^ 1;
        float frn = (act && t + 2 < Tn) ? g_feats[(size_t)(t + 2) * Ln + to] : 0.f;

        // load full alpha via 5 vectorized broadcast LDS
        float av[20];
        {
            const float4* ap = (const float4*)al[b];
            float4 v0 = ap[0], v1 = ap[1], v2 = ap[2], v3 = ap[3], v4 = ap[4];
            av[0] = v0.x;  av[1] = v0.y;  av[2] = v0.z;  av[3] = v0.w;
            av[4] = v1.x;  av[5] = v1.y;  av[6] = v1.z;  av[7] = v1.w;
            av[8] = v2.x;  av[9] = v2.y;  av[10] = v2.z; av[11] = v2.w;
            av[12] = v3.x; av[13] = v3.y; av[14] = v3.z; av[15] = v3.w;
            av[16] = v4.x; av[17] = v4.y; av[18] = v4.z; av[19] = v4.w;
        }

        float s[Ln];
#pragma unroll
        for (int f = 0; f < Ln; f++) s[f] = av[f] + tr[f];

        float m[10];
#pragma unroll
        for (int i = 0; i < 10; i++) m[i] = fmaxf(s[i], s[i + 10]);
#pragma unroll
        for (int i = 0; i < 5; i++) m[i] = fmaxf(m[i], m[i + 5]);
        float best = fmaxf(fmaxf(fmaxf(m[0], m[1]), fmaxf(m[2], m[3])), m[4]);

        unsigned msk = 0;
#pragma unroll
        for (int f = 0; f < Ln; f++)
            msk |= (s[f] == best) ? (1u << f) : 0u;
        int arg = __ffs(msk) - 1;   // first (lowest) index, matches jnp.argmax

        if (act) {
            bp[(size_t)t * Ln + to] = (unsigned char)arg;
            alpha = best + fr0;
            al[nb][to] = alpha;
        }
        __syncwarp();
        fr0 = fr1;
        fr1 = frn;
    }

    float fin = act ? (alpha + trstop) : -1e30f;
    float best = fin;
#pragma unroll
    for (int o = 16; o; o >>= 1) best = fmaxf(best, __shfl_xor_sync(0xffffffffu, best, o));
    unsigned msk = __ballot_sync(0xffffffffu, fin == best);
    int best_last = __ffs(msk) - 1;

    if (lane == 0) {
        float* po = out;
        if (out_size >= Tn + 1) { out[0] = best; po = out + 1; }
        int cur = best_last;
        po[Tn - 1] = (float)cur;
        for (int t = Tn - 1; t >= 1; t--) {
            cur = bp[(size_t)t * Ln + cur];
            po[t - 1] = (float)cur;
        }
        if (out_size == 1) out[0] = best;
    }
}

// ---------------- launch ------------------------------------------------------
extern "C" void kernel_launch(void* const* d_in, const int* in_sizes, int n_in,
                              void* d_out, int out_size) {
    const int*   x      = (const int*)  d_in[0];
    const float* emb    = (const float*)d_in[1];
    const float* wih_f  = (const float*)d_in[2];
    const float* whh_f  = (const float*)d_in[3];
    const float* bih_f  = (const float*)d_in[4];
    const float* bhh_f  = (const float*)d_in[5];
    const float* wih_b  = (const float*)d_in[6];
    const float* whh_b  = (const float*)d_in[7];
    const float* bih_b  = (const float*)d_in[8];
    const float* bhh_b  = (const float*)d_in[9];
    const float* wout   = (const float*)d_in[10];
    const float* bout   = (const float*)d_in[11];
    const float* trans  = (const float*)d_in[12];
    const float* h0     = (const float*)d_in[13];
    const float* c0     = (const float*)d_in[14];
    float* out = (float*)d_out;

    gather_kernel<<<Tn, 64>>>(x, emb);

    // keeps ncu's positional capture slot on lstm_dir16
    profile_shift_kernel<<<1, 32>>>();

    dim3 zg(Tn / 64, G4 / 64, 2);
    zgemm_kernel<<<zg, 256>>>(wih_f, bih_f, bhh_f, wih_b, bih_b, bhh_b);

    // two 16-CTA clusters (one per direction); fallback to proven 8-CTA kernel
    cudaFuncSetAttribute(lstm_dir16,
                         cudaFuncAttributeNonPortableClusterSizeAllowed, 1);
    cudaLaunchConfig_t cfg = {};
    cfg.gridDim = dim3(32, 1, 1);
    cfg.blockDim = dim3(256, 1, 1);
    cfg.dynamicSmemBytes = 0;
    cudaLaunchAttribute attrs[1];
    attrs[0].id = cudaLaunchAttributeClusterDimension;
    attrs[0].val.clusterDim = {16, 1, 1};
    cfg.attrs = attrs;
    cfg.numAttrs = 1;
    cudaError_t e = cudaLaunchKernelEx(&cfg, lstm_dir16, whh_f, whh_b, h0, c0);
    if (e != cudaSuccess) {
        (void)cudaGetLastError();   // clear
        lstm_fallback<<<16, 256>>>(whh_f, whh_b, h0, c0);
    }

    feats_kernel<<<Tn, Ln * 32>>>(wout, bout);

    int vit_smem = Tn * Ln;  // 80 KB backpointers (dynamic)
    cudaFuncSetAttribute(viterbi_kernel,
                         cudaFuncAttributeMaxDynamicSharedMemorySize, vit_smem);
    viterbi_kernel<<<1, 32, vit_smem>>>(trans, out, out_size);
}